// round 5
// baseline (speedup 1.0000x reference)
#include <cuda_runtime.h>
#include <math.h>

// Problem constants
static constexpr int B  = 2;
static constexpr int S  = 2048;
static constexpr int D  = 512;
static constexpr int H  = 8;
static constexpr int DK = 64;
static constexpr int M_TOT = B * S;   // 4096

// Scratch (no allocations allowed)
__device__ float g_q[M_TOT * D];
__device__ float g_k[M_TOT * D];
__device__ float g_v[M_TOT * D];
__device__ float g_x[M_TOT * D];

// ---------------------------------------------------------------------------
// Packed fp32x2 helpers (sm_103a). fma.rn.f32x2 = two independent fma.rn.f32
// in one fma-pipe slot -> 2x fp32 FMA ceiling. ptxas never emits it from C++.
// ---------------------------------------------------------------------------
typedef unsigned long long u64;

__device__ __forceinline__ u64 pk2(float lo, float hi) {
    u64 r;
    asm("mov.b64 %0, {%1, %2};" : "=l"(r) : "f"(lo), "f"(hi));
    return r;
}
__device__ __forceinline__ u64 dup2(float v) {
    u64 r;
    asm("mov.b64 %0, {%1, %1};" : "=l"(r) : "f"(v));
    return r;
}
__device__ __forceinline__ void upk2(u64 p, float& lo, float& hi) {
    asm("mov.b64 {%0, %1}, %2;" : "=f"(lo), "=f"(hi) : "l"(p));
}
__device__ __forceinline__ u64 ffma2(u64 a, u64 b, u64 c) {
    u64 d;
    asm("fma.rn.f32x2 %0, %1, %2, %3;" : "=l"(d) : "l"(a), "l"(b), "l"(c));
    return d;
}
__device__ __forceinline__ u64 fmul2(u64 a, u64 b) {
    u64 d;
    asm("mul.rn.f32x2 %0, %1, %2;" : "=l"(d) : "l"(a), "l"(b));
    return d;
}

// ---------------------------------------------------------------------------
// GEMM body: Y[4096,512] = X[4096,512] @ W[512,512]^T + bias  (torch Linear)
// BM=BN=64, BK=32, 256 threads, 4x4 microtile, DOUBLE-BUFFERED smem.
// Tiles stored transposed [k][m] stride 68 (conflict-free float4 reads).
// Inner loop uses packed FFMA2: 8 FFMA2 per k-step instead of 16 FFMA.
// ---------------------------------------------------------------------------
static constexpr int GBK = 32, GST = 68;
static constexpr int TILE_F = GBK * GST;   // floats per tile buffer (2176)

__device__ __forceinline__ void gemm512_body(
    const float* __restrict__ X, const float* __restrict__ W,
    const float* __restrict__ bias, float* __restrict__ Y,
    float* As, float* Bs)    // each sized 2*TILE_F
{
    const int tid = threadIdx.x;
    const int tx = tid & 15;
    const int ty = tid >> 4;
    const int m0 = blockIdx.y * 64;
    const int n0 = blockIdx.x * 64;

    // loader coordinates (2 float4 per thread per tile)
    const int r0 = tid >> 3;            // it=0 row
    const int r1 = (tid + 256) >> 3;    // it=1 row
    const int c40 = tid & 7;            // k/4 (same for both its)

    u64 acc2[4][2];
    const u64 z2 = pk2(0.0f, 0.0f);
#pragma unroll
    for (int i = 0; i < 4; i++) { acc2[i][0] = z2; acc2[i][1] = z2; }

    float4 ra0, ra1, rb0, rb1;

    // prologue: fetch tile k0=0
    ra0 = *reinterpret_cast<const float4*>(X + (size_t)(m0 + r0) * D + c40 * 4);
    ra1 = *reinterpret_cast<const float4*>(X + (size_t)(m0 + r1) * D + c40 * 4);
    rb0 = *reinterpret_cast<const float4*>(W + (size_t)(n0 + r0) * D + c40 * 4);
    rb1 = *reinterpret_cast<const float4*>(W + (size_t)(n0 + r1) * D + c40 * 4);
    {
        float* A = As; float* Bt = Bs;
        A[(c40 * 4 + 0) * GST + r0] = ra0.x; A[(c40 * 4 + 1) * GST + r0] = ra0.y;
        A[(c40 * 4 + 2) * GST + r0] = ra0.z; A[(c40 * 4 + 3) * GST + r0] = ra0.w;
        A[(c40 * 4 + 0) * GST + r1] = ra1.x; A[(c40 * 4 + 1) * GST + r1] = ra1.y;
        A[(c40 * 4 + 2) * GST + r1] = ra1.z; A[(c40 * 4 + 3) * GST + r1] = ra1.w;
        Bt[(c40 * 4 + 0) * GST + r0] = rb0.x; Bt[(c40 * 4 + 1) * GST + r0] = rb0.y;
        Bt[(c40 * 4 + 2) * GST + r0] = rb0.z; Bt[(c40 * 4 + 3) * GST + r0] = rb0.w;
        Bt[(c40 * 4 + 0) * GST + r1] = rb1.x; Bt[(c40 * 4 + 1) * GST + r1] = rb1.y;
        Bt[(c40 * 4 + 2) * GST + r1] = rb1.z; Bt[(c40 * 4 + 3) * GST + r1] = rb1.w;
    }
    __syncthreads();

    int buf = 0;
    for (int k0 = 0; k0 < D; k0 += GBK, buf ^= 1) {
        const bool more = (k0 + GBK) < D;
        if (more) {  // early gmem fetch of next tile (overlaps with compute)
            const int kn = k0 + GBK;
            ra0 = *reinterpret_cast<const float4*>(X + (size_t)(m0 + r0) * D + kn + c40 * 4);
            ra1 = *reinterpret_cast<const float4*>(X + (size_t)(m0 + r1) * D + kn + c40 * 4);
            rb0 = *reinterpret_cast<const float4*>(W + (size_t)(n0 + r0) * D + kn + c40 * 4);
            rb1 = *reinterpret_cast<const float4*>(W + (size_t)(n0 + r1) * D + kn + c40 * 4);
        }

        const float* A = As + buf * TILE_F;
        const float* Bt = Bs + buf * TILE_F;
#pragma unroll
        for (int kk = 0; kk < GBK; kk++) {
            float4 a4 = *reinterpret_cast<const float4*>(A + kk * GST + ty * 4);
            float4 b4 = *reinterpret_cast<const float4*>(Bt + kk * GST + tx * 4);
            u64 b01 = pk2(b4.x, b4.y);   // aligned pair from LDS.128 -> coalesced
            u64 b23 = pk2(b4.z, b4.w);
            float a[4] = {a4.x, a4.y, a4.z, a4.w};
#pragma unroll
            for (int i = 0; i < 4; i++) {
                u64 ad = dup2(a[i]);
                acc2[i][0] = ffma2(ad, b01, acc2[i][0]);
                acc2[i][1] = ffma2(ad, b23, acc2[i][1]);
            }
        }

        if (more) {  // stores to the other buffer; its readers finished before
                     // the sync that ended the previous iteration
            float* An = As + (buf ^ 1) * TILE_F;
            float* Bn = Bs + (buf ^ 1) * TILE_F;
            An[(c40 * 4 + 0) * GST + r0] = ra0.x; An[(c40 * 4 + 1) * GST + r0] = ra0.y;
            An[(c40 * 4 + 2) * GST + r0] = ra0.z; An[(c40 * 4 + 3) * GST + r0] = ra0.w;
            An[(c40 * 4 + 0) * GST + r1] = ra1.x; An[(c40 * 4 + 1) * GST + r1] = ra1.y;
            An[(c40 * 4 + 2) * GST + r1] = ra1.z; An[(c40 * 4 + 3) * GST + r1] = ra1.w;
            Bn[(c40 * 4 + 0) * GST + r0] = rb0.x; Bn[(c40 * 4 + 1) * GST + r0] = rb0.y;
            Bn[(c40 * 4 + 2) * GST + r0] = rb0.z; Bn[(c40 * 4 + 3) * GST + r0] = rb0.w;
            Bn[(c40 * 4 + 0) * GST + r1] = rb1.x; Bn[(c40 * 4 + 1) * GST + r1] = rb1.y;
            Bn[(c40 * 4 + 2) * GST + r1] = rb1.z; Bn[(c40 * 4 + 3) * GST + r1] = rb1.w;
        }
        __syncthreads();
    }

    const float4 b4 = *reinterpret_cast<const float4*>(bias + n0 + tx * 4);
#pragma unroll
    for (int i = 0; i < 4; i++) {
        float a0, a1, a2, a3;
        upk2(acc2[i][0], a0, a1);
        upk2(acc2[i][1], a2, a3);
        float4 o;
        o.x = a0 + b4.x;
        o.y = a1 + b4.y;
        o.z = a2 + b4.z;
        o.w = a3 + b4.w;
        *reinterpret_cast<float4*>(
            Y + (size_t)(m0 + ty * 4 + i) * D + n0 + tx * 4) = o;
    }
}

// Fused Q/K/V projections: blockIdx.z selects which projection.
__global__ __launch_bounds__(256) void qkv_gemm_kernel(
    const float* __restrict__ query, const float* __restrict__ key,
    const float* __restrict__ value,
    const float* __restrict__ Wq, const float* __restrict__ bq,
    const float* __restrict__ Wk, const float* __restrict__ bk,
    const float* __restrict__ Wv, const float* __restrict__ bv)
{
    __shared__ float As[2 * TILE_F];
    __shared__ float Bs[2 * TILE_F];
    const int z = blockIdx.z;
    const float* X = (z == 0) ? query : (z == 1) ? key : value;
    const float* W = (z == 0) ? Wq : (z == 1) ? Wk : Wv;
    const float* bias = (z == 0) ? bq : (z == 1) ? bk : bv;
    float* Y = (z == 0) ? g_q : (z == 1) ? g_k : g_v;
    gemm512_body(X, W, bias, Y, As, Bs);
}

// Output projection: out = g_x @ Wo^T + bo
__global__ __launch_bounds__(256) void out_gemm_kernel(
    const float* __restrict__ Wo, const float* __restrict__ bo,
    float* __restrict__ out)
{
    __shared__ float As[2 * TILE_F];
    __shared__ float Bs[2 * TILE_F];
    gemm512_body(g_x, Wo, bo, out, As, Bs);
}

// ---------------------------------------------------------------------------
// Causal flash attention g_q/g_k/g_v -> g_x (merged-head layout).
// Grid: (S/64, H, B), 256 threads, 4x4 microtiles (FFMA2-packed along j).
// Qt/Kt transposed [d][row] stride 68; V row-major stride 64; P transposed
// [c][r] stride 68 (PV-phase P reads are broadcast float4).
// K/V tiles register-prefetched one kv-block ahead. qb reversed so the
// longest CTAs launch first.
// Smem floats: Qt 64*68 + Kt 64*68 + Vs 64*64 + Pt 64*68 = 17152 = 68608 B.
// ---------------------------------------------------------------------------
__global__ __launch_bounds__(256) void attn_kernel()
{
    constexpr int BQ = 64, BKV = 64, ST = 68;
    extern __shared__ float sm[];
    float* Qt = sm;                       // Qt[d*ST + r]
    float* Kt = sm + 64 * ST;             // Kt[d*ST + c]
    float* Vs = sm + 2 * 64 * ST;         // Vs[c*64 + d]
    float* Pt = sm + 2 * 64 * ST + 4096;  // Pt[c*ST + r]

    const int tid = threadIdx.x;
    const int tx = tid & 15;
    const int ty = tid >> 4;
    const int qb = gridDim.x - 1 - blockIdx.x;   // longest CTAs first
    const int h  = blockIdx.y;
    const int b  = blockIdx.z;

    const float* qbase = g_q + ((size_t)b * S + qb * BQ) * D + h * DK;
    const float* kbase = g_k + (size_t)b * S * D + h * DK;
    const float* vbase = g_v + (size_t)b * S * D + h * DK;

    // loader coords: c4 = d/4 (constant per thread), rows (tid>>4)+16*it
    const int lc4 = tid & 15;
    const int lr  = tid >> 4;

    // Load Q tile transposed: 1024 float4, 4 per thread.
#pragma unroll
    for (int it = 0; it < 4; it++) {
        int row = lr + it * 16;
        float4 v = *reinterpret_cast<const float4*>(qbase + (size_t)row * D + lc4 * 4);
        Qt[(lc4 * 4 + 0) * ST + row] = v.x;
        Qt[(lc4 * 4 + 1) * ST + row] = v.y;
        Qt[(lc4 * 4 + 2) * ST + row] = v.z;
        Qt[(lc4 * 4 + 3) * ST + row] = v.w;
    }

    float m[4], l[4];
    u64 O2[4][2];
    const u64 z2 = pk2(0.0f, 0.0f);
#pragma unroll
    for (int i = 0; i < 4; i++) {
        m[i] = -1e30f; l[i] = 0.0f;
        O2[i][0] = z2; O2[i][1] = z2;
    }

    // Prologue: prefetch K/V tile for kb=0 into registers.
    float4 kpre[4], vpre[4];
#pragma unroll
    for (int it = 0; it < 4; it++) {
        int row = lr + it * 16;
        kpre[it] = *reinterpret_cast<const float4*>(kbase + (size_t)row * D + lc4 * 4);
        vpre[it] = *reinterpret_cast<const float4*>(vbase + (size_t)row * D + lc4 * 4);
    }

    const int nkb = qb + 1;   // causal: key blocks kb <= qb only
    for (int kb = 0; kb < nkb; kb++) {
        __syncthreads();   // prior PV (Vs) and score (Kt) reads done; Qt stored

        // Store prefetched registers to smem.
#pragma unroll
        for (int it = 0; it < 4; it++) {
            int row = lr + it * 16;
            float4 kv = kpre[it];
            Kt[(lc4 * 4 + 0) * ST + row] = kv.x;
            Kt[(lc4 * 4 + 1) * ST + row] = kv.y;
            Kt[(lc4 * 4 + 2) * ST + row] = kv.z;
            Kt[(lc4 * 4 + 3) * ST + row] = kv.w;
            float4 vv = vpre[it];
            float* vd = Vs + row * 64 + lc4 * 4;
            vd[0] = vv.x; vd[1] = vv.y; vd[2] = vv.z; vd[3] = vv.w;
        }
        __syncthreads();

        // Prefetch next kv block (latency hidden by score/softmax/PV below).
        if (kb + 1 < nkb) {
            const float* kt = kbase + (size_t)((kb + 1) * BKV) * D;
            const float* vt = vbase + (size_t)((kb + 1) * BKV) * D;
#pragma unroll
            for (int it = 0; it < 4; it++) {
                int row = lr + it * 16;
                kpre[it] = *reinterpret_cast<const float4*>(kt + (size_t)row * D + lc4 * 4);
                vpre[it] = *reinterpret_cast<const float4*>(vt + (size_t)row * D + lc4 * 4);
            }
        }

        // Scores (packed): s2[i][p] = pairs (j=2p, j=2p+1)
        u64 s2[4][2];
#pragma unroll
        for (int i = 0; i < 4; i++) { s2[i][0] = z2; s2[i][1] = z2; }

#pragma unroll 8
        for (int d = 0; d < DK; d++) {
            float4 q4 = *reinterpret_cast<const float4*>(Qt + d * ST + ty * 4);
            float4 k4 = *reinterpret_cast<const float4*>(Kt + d * ST + tx * 4);
            u64 k01 = pk2(k4.x, k4.y);
            u64 k23 = pk2(k4.z, k4.w);
            float qv[4] = {q4.x, q4.y, q4.z, q4.w};
#pragma unroll
            for (int i = 0; i < 4; i++) {
                u64 qd = dup2(qv[i]);
                s2[i][0] = ffma2(qd, k01, s2[i][0]);
                s2[i][1] = ffma2(qd, k23, s2[i][1]);
            }
        }

        // Unpack, scale, mask (scalar — once per tile).
        float s[4][4];
#pragma unroll
        for (int i = 0; i < 4; i++) {
            upk2(s2[i][0], s[i][0], s[i][1]);
            upk2(s2[i][1], s[i][2], s[i][3]);
        }
        const float scale = 0.125f;  // 1/sqrt(64)
#pragma unroll
        for (int i = 0; i < 4; i++)
#pragma unroll
            for (int j = 0; j < 4; j++) s[i][j] *= scale;

        if (kb == qb) {
#pragma unroll
            for (int i = 0; i < 4; i++)
#pragma unroll
                for (int j = 0; j < 4; j++)
                    if (tx * 4 + j > ty * 4 + i) s[i][j] = -1e30f;
        }

        // Online softmax (row state duplicated across the 16 tx lanes).
#pragma unroll
        for (int i = 0; i < 4; i++) {
            float rm = fmaxf(fmaxf(s[i][0], s[i][1]), fmaxf(s[i][2], s[i][3]));
#pragma unroll
            for (int off = 8; off >= 1; off >>= 1)
                rm = fmaxf(rm, __shfl_xor_sync(0xffffffffu, rm, off));
            float mn   = fmaxf(m[i], rm);
            float corr = __expf(m[i] - mn);
            float rs = 0.0f;
#pragma unroll
            for (int j = 0; j < 4; j++) {
                float p = __expf(s[i][j] - mn);
                Pt[(tx * 4 + j) * ST + ty * 4 + i] = p;   // transposed store
                rs += p;
            }
#pragma unroll
            for (int off = 8; off >= 1; off >>= 1)
                rs += __shfl_xor_sync(0xffffffffu, rs, off);
            l[i] = l[i] * corr + rs;
            m[i] = mn;
            u64 cd = dup2(corr);
            O2[i][0] = fmul2(cd, O2[i][0]);
            O2[i][1] = fmul2(cd, O2[i][1]);
        }
        __syncthreads();

        // O2[i][p] += P[row_i][c] * V[c][pair p]; P read = broadcast float4
#pragma unroll 8
        for (int c = 0; c < BKV; c++) {
            float4 p4 = *reinterpret_cast<const float4*>(Pt + c * ST + ty * 4);
            float4 v4 = *reinterpret_cast<const float4*>(Vs + c * 64 + tx * 4);
            u64 v01 = pk2(v4.x, v4.y);
            u64 v23 = pk2(v4.z, v4.w);
            float pr[4] = {p4.x, p4.y, p4.z, p4.w};
#pragma unroll
            for (int i = 0; i < 4; i++) {
                u64 pd = dup2(pr[i]);
                O2[i][0] = ffma2(pd, v01, O2[i][0]);
                O2[i][1] = ffma2(pd, v23, O2[i][1]);
            }
        }
    }

    // Normalize, write merged-head output g_x[b, q, h*DK + d] (float4).
#pragma unroll
    for (int i = 0; i < 4; i++) {
        float inv = 1.0f / l[i];
        float o0, o1, o2, o3;
        upk2(O2[i][0], o0, o1);
        upk2(O2[i][1], o2, o3);
        float4 o;
        o.x = o0 * inv; o.y = o1 * inv;
        o.z = o2 * inv; o.w = o3 * inv;
        *reinterpret_cast<float4*>(
            g_x + ((size_t)b * S + qb * BQ + ty * 4 + i) * D + h * DK + tx * 4) = o;
    }
}

// ---------------------------------------------------------------------------
// inputs: 0=query 1=key 2=value 3=mask(causal tril, implemented inline)
//         4=Wq 5=bq 6=Wk 7=bk 8=Wv 9=bv 10=Wo 11=bo ; output float [B,S,D]
// ---------------------------------------------------------------------------
extern "C" void kernel_launch(void* const* d_in, const int* in_sizes, int n_in,
                              void* d_out, int out_size)
{
    const float* query = (const float*)d_in[0];
    const float* key   = (const float*)d_in[1];
    const float* value = (const float*)d_in[2];
    const float* Wq = (const float*)d_in[4];
    const float* bq = (const float*)d_in[5];
    const float* Wk = (const float*)d_in[6];
    const float* bk = (const float*)d_in[7];
    const float* Wv = (const float*)d_in[8];
    const float* bv = (const float*)d_in[9];
    const float* Wo = (const float*)d_in[10];
    const float* bo = (const float*)d_in[11];
    float* out = (float*)d_out;

    cudaFuncSetAttribute(attn_kernel,
                         cudaFuncAttributeMaxDynamicSharedMemorySize, 68608);

    dim3 qkv_grid(D / 64, M_TOT / 64, 3);   // (8, 64, 3) = 1536 CTAs
    qkv_gemm_kernel<<<qkv_grid, 256>>>(query, key, value,
                                       Wq, bq, Wk, bk, Wv, bv);

    dim3 agrid(S / 64, H, B);               // (32, 8, 2)
    attn_kernel<<<agrid, 256, 68608>>>();

    dim3 ogrid(D / 64, M_TOT / 64);         // (8, 64)
    out_gemm_kernel<<<ogrid, 256>>>(Wo, bo, out);
}

// round 8
// speedup vs baseline: 1.0252x; 1.0252x over previous
#include <cuda_runtime.h>
#include <math.h>

// Problem constants
static constexpr int B  = 2;
static constexpr int S  = 2048;
static constexpr int D  = 512;
static constexpr int H  = 8;
static constexpr int DK = 64;
static constexpr int M_TOT = B * S;   // 4096

// Scratch (no allocations allowed)
__device__ float g_q[M_TOT * D];
__device__ float g_k[M_TOT * D];
__device__ float g_v[M_TOT * D];
__device__ float g_x[M_TOT * D];

// ---------------------------------------------------------------------------
// Packed fp32x2 helpers (sm_103a): fma.rn.f32x2 = 2 independent fp32 FMA per
// fma-pipe slot. Bit-identical to scalar fma.rn.f32.
// ---------------------------------------------------------------------------
typedef unsigned long long u64;

__device__ __forceinline__ u64 pk2(float lo, float hi) {
    u64 r;
    asm("mov.b64 %0, {%1, %2};" : "=l"(r) : "f"(lo), "f"(hi));
    return r;
}
__device__ __forceinline__ u64 dup2(float v) {
    u64 r;
    asm("mov.b64 %0, {%1, %1};" : "=l"(r) : "f"(v));
    return r;
}
__device__ __forceinline__ void upk2(u64 p, float& lo, float& hi) {
    asm("mov.b64 {%0, %1}, %2;" : "=f"(lo), "=f"(hi) : "l"(p));
}
__device__ __forceinline__ u64 ffma2(u64 a, u64 b, u64 c) {
    u64 d;
    asm("fma.rn.f32x2 %0, %1, %2, %3;" : "=l"(d) : "l"(a), "l"(b), "l"(c));
    return d;
}
__device__ __forceinline__ u64 fmul2(u64 a, u64 b) {
    u64 d;
    asm("mul.rn.f32x2 %0, %1, %2;" : "=l"(d) : "l"(a), "l"(b));
    return d;
}

// ---------------------------------------------------------------------------
// GEMM: Y[4096,512] = X[4096,512] @ W[512,512]^T + bias  (torch Linear)
// 128x128 block tile, BK=16, 256 threads, 8x8 microtile (FFMA2), double-
// buffered smem with register prefetch.
// Per k-step: 4 LDS.128 + 32 FFMA2 (LDS/FFMA2 = 0.125, half of R5).
// Column split: each thread owns cols [tx*4, tx*4+4) and [64+tx*4, 64+tx*4+4)
// so every b-LDS.128 has 16B lane stride (bandwidth-minimum, no conflicts).
// ---------------------------------------------------------------------------
static constexpr int GBK = 16, GST = 132;        // 128 + 4 pad
static constexpr int TILE_F = GBK * GST;         // 2112 floats per buffer

__device__ __forceinline__ void gemm512_body(
    const float* __restrict__ X, const float* __restrict__ W,
    const float* __restrict__ bias, float* __restrict__ Y,
    float* As, float* Bs)    // each sized 2*TILE_F
{
    const int tid = threadIdx.x;
    const int tx = tid & 15;            // column group
    const int ty = tid >> 4;            // row group (8 rows each)
    const int m0 = blockIdx.y * 128;
    const int n0 = blockIdx.x * 128;

    // loader coords: 2 float4 per operand per thread per tile
    const int r0 = tid >> 2;            // rows 0..63
    const int r1 = (tid + 256) >> 2;    // rows 64..127
    const int c40 = tid & 3;            // k/4 within BK=16

    u64 acc2[8][4];
    const u64 z2 = pk2(0.0f, 0.0f);
#pragma unroll
    for (int i = 0; i < 8; i++)
#pragma unroll
        for (int p = 0; p < 4; p++) acc2[i][p] = z2;

    float4 ra0, ra1, rb0, rb1;

    // prologue: fetch tile k0=0
    ra0 = *reinterpret_cast<const float4*>(X + (size_t)(m0 + r0) * D + c40 * 4);
    ra1 = *reinterpret_cast<const float4*>(X + (size_t)(m0 + r1) * D + c40 * 4);
    rb0 = *reinterpret_cast<const float4*>(W + (size_t)(n0 + r0) * D + c40 * 4);
    rb1 = *reinterpret_cast<const float4*>(W + (size_t)(n0 + r1) * D + c40 * 4);
    {
        float* A = As; float* Bt = Bs;
        A[(c40 * 4 + 0) * GST + r0] = ra0.x; A[(c40 * 4 + 1) * GST + r0] = ra0.y;
        A[(c40 * 4 + 2) * GST + r0] = ra0.z; A[(c40 * 4 + 3) * GST + r0] = ra0.w;
        A[(c40 * 4 + 0) * GST + r1] = ra1.x; A[(c40 * 4 + 1) * GST + r1] = ra1.y;
        A[(c40 * 4 + 2) * GST + r1] = ra1.z; A[(c40 * 4 + 3) * GST + r1] = ra1.w;
        Bt[(c40 * 4 + 0) * GST + r0] = rb0.x; Bt[(c40 * 4 + 1) * GST + r0] = rb0.y;
        Bt[(c40 * 4 + 2) * GST + r0] = rb0.z; Bt[(c40 * 4 + 3) * GST + r0] = rb0.w;
        Bt[(c40 * 4 + 0) * GST + r1] = rb1.x; Bt[(c40 * 4 + 1) * GST + r1] = rb1.y;
        Bt[(c40 * 4 + 2) * GST + r1] = rb1.z; Bt[(c40 * 4 + 3) * GST + r1] = rb1.w;
    }
    __syncthreads();

    int buf = 0;
    for (int k0 = 0; k0 < D; k0 += GBK, buf ^= 1) {
        const bool more = (k0 + GBK) < D;
        if (more) {  // early gmem fetch of next tile (overlaps compute)
            const int kn = k0 + GBK;
            ra0 = *reinterpret_cast<const float4*>(X + (size_t)(m0 + r0) * D + kn + c40 * 4);
            ra1 = *reinterpret_cast<const float4*>(X + (size_t)(m0 + r1) * D + kn + c40 * 4);
            rb0 = *reinterpret_cast<const float4*>(W + (size_t)(n0 + r0) * D + kn + c40 * 4);
            rb1 = *reinterpret_cast<const float4*>(W + (size_t)(n0 + r1) * D + kn + c40 * 4);
        }

        const float* A = As + buf * TILE_F;
        const float* Bt = Bs + buf * TILE_F;
#pragma unroll
        for (int kk = 0; kk < GBK; kk++) {
            float4 a0 = *reinterpret_cast<const float4*>(A + kk * GST + ty * 8);
            float4 a1 = *reinterpret_cast<const float4*>(A + kk * GST + ty * 8 + 4);
            float4 b0 = *reinterpret_cast<const float4*>(Bt + kk * GST + tx * 4);
            float4 b1 = *reinterpret_cast<const float4*>(Bt + kk * GST + 64 + tx * 4);
            u64 bp[4] = {pk2(b0.x, b0.y), pk2(b0.z, b0.w),
                         pk2(b1.x, b1.y), pk2(b1.z, b1.w)};
            float a[8] = {a0.x, a0.y, a0.z, a0.w, a1.x, a1.y, a1.z, a1.w};
#pragma unroll
            for (int i = 0; i < 8; i++) {
                u64 ad = dup2(a[i]);
#pragma unroll
                for (int p = 0; p < 4; p++)
                    acc2[i][p] = ffma2(ad, bp[p], acc2[i][p]);
            }
        }

        if (more) {  // stores to the other buffer
            float* An = As + (buf ^ 1) * TILE_F;
            float* Bn = Bs + (buf ^ 1) * TILE_F;
            An[(c40 * 4 + 0) * GST + r0] = ra0.x; An[(c40 * 4 + 1) * GST + r0] = ra0.y;
            An[(c40 * 4 + 2) * GST + r0] = ra0.z; An[(c40 * 4 + 3) * GST + r0] = ra0.w;
            An[(c40 * 4 + 0) * GST + r1] = ra1.x; An[(c40 * 4 + 1) * GST + r1] = ra1.y;
            An[(c40 * 4 + 2) * GST + r1] = ra1.z; An[(c40 * 4 + 3) * GST + r1] = ra1.w;
            Bn[(c40 * 4 + 0) * GST + r0] = rb0.x; Bn[(c40 * 4 + 1) * GST + r0] = rb0.y;
            Bn[(c40 * 4 + 2) * GST + r0] = rb0.z; Bn[(c40 * 4 + 3) * GST + r0] = rb0.w;
            Bn[(c40 * 4 + 0) * GST + r1] = rb1.x; Bn[(c40 * 4 + 1) * GST + r1] = rb1.y;
            Bn[(c40 * 4 + 2) * GST + r1] = rb1.z; Bn[(c40 * 4 + 3) * GST + r1] = rb1.w;
        }
        __syncthreads();
    }

    const float4 bb0 = *reinterpret_cast<const float4*>(bias + n0 + tx * 4);
    const float4 bb1 = *reinterpret_cast<const float4*>(bias + n0 + 64 + tx * 4);
#pragma unroll
    for (int i = 0; i < 8; i++) {
        float c0, c1, c2, c3;
        upk2(acc2[i][0], c0, c1);
        upk2(acc2[i][1], c2, c3);
        float4 o0 = {c0 + bb0.x, c1 + bb0.y, c2 + bb0.z, c3 + bb0.w};
        upk2(acc2[i][2], c0, c1);
        upk2(acc2[i][3], c2, c3);
        float4 o1 = {c0 + bb1.x, c1 + bb1.y, c2 + bb1.z, c3 + bb1.w};
        float* yrow = Y + (size_t)(m0 + ty * 8 + i) * D + n0;
        *reinterpret_cast<float4*>(yrow + tx * 4) = o0;
        *reinterpret_cast<float4*>(yrow + 64 + tx * 4) = o1;
    }
}

// Fused Q/K/V projections: blockIdx.z selects which projection.
__global__ __launch_bounds__(256, 2) void qkv_gemm_kernel(
    const float* __restrict__ query, const float* __restrict__ key,
    const float* __restrict__ value,
    const float* __restrict__ Wq, const float* __restrict__ bq,
    const float* __restrict__ Wk, const float* __restrict__ bk,
    const float* __restrict__ Wv, const float* __restrict__ bv)
{
    __shared__ float As[2 * TILE_F];
    __shared__ float Bs[2 * TILE_F];
    const int z = blockIdx.z;
    const float* X = (z == 0) ? query : (z == 1) ? key : value;
    const float* W = (z == 0) ? Wq : (z == 1) ? Wk : Wv;
    const float* bias = (z == 0) ? bq : (z == 1) ? bk : bv;
    float* Y = (z == 0) ? g_q : (z == 1) ? g_k : g_v;
    gemm512_body(X, W, bias, Y, As, Bs);
}

// Output projection: out = g_x @ Wo^T + bo
__global__ __launch_bounds__(256, 2) void out_gemm_kernel(
    const float* __restrict__ Wo, const float* __restrict__ bo,
    float* __restrict__ out)
{
    __shared__ float As[2 * TILE_F];
    __shared__ float Bs[2 * TILE_F];
    gemm512_body(g_x, Wo, bo, out, As, Bs);
}

// ---------------------------------------------------------------------------
// Causal flash attention g_q/g_k/g_v -> g_x (merged-head layout).
// BQ=128 q rows per CTA, BKV=64. Grid: (S/128, H, B) = (16,8,2) = 256 CTAs.
// 256 threads, 8x4 microtile (8 q rows x 4 kv cols / head dims per thread).
// Qt/Kt transposed [d][row]; V row-major; P transposed [c][r].
// Smem floats: Qt 64*132 + Kt 64*68 + Vs 64*64 + Pt 64*132 = 25344 = 101376 B
// -> 2 CTAs/SM (launch_bounds forces regs <= 128).
// ---------------------------------------------------------------------------
__global__ __launch_bounds__(256, 2) void attn_kernel()
{
    constexpr int BQ = 128, BKV = 64, QST = 132, KST = 68;
    extern __shared__ float sm[];
    float* Qt = sm;                 // Qt[d*QST + r], r 0..127
    float* Kt = sm + 8448;          // Kt[d*KST + c], c 0..63
    float* Vs = sm + 12800;         // Vs[c*64 + dk]
    float* Pt = sm + 16896;         // Pt[c*QST + r]

    const int tid = threadIdx.x;
    const int tx = tid & 15;
    const int ty = tid >> 4;
    const int qb = gridDim.x - 1 - blockIdx.x;   // longest CTAs first
    const int h  = blockIdx.y;
    const int b  = blockIdx.z;

    const float* qbase = g_q + ((size_t)b * S + qb * BQ) * D + h * DK;
    const float* kbase = g_k + (size_t)b * S * D + h * DK;
    const float* vbase = g_v + (size_t)b * S * D + h * DK;

    // Q loader: 128 rows x 16 f4 = 2048 f4 / 256 thr = 8 each
    {
        const int c4 = tid & 15;
#pragma unroll
        for (int it = 0; it < 8; it++) {
            int row = (tid >> 4) + it * 16;
            float4 v = *reinterpret_cast<const float4*>(qbase + (size_t)row * D + c4 * 4);
            Qt[(c4 * 4 + 0) * QST + row] = v.x;
            Qt[(c4 * 4 + 1) * QST + row] = v.y;
            Qt[(c4 * 4 + 2) * QST + row] = v.z;
            Qt[(c4 * 4 + 3) * QST + row] = v.w;
        }
    }

    float m[8], l[8];
    u64 O2[8][2];
    const u64 z2 = pk2(0.0f, 0.0f);
#pragma unroll
    for (int i = 0; i < 8; i++) {
        m[i] = -1e30f; l[i] = 0.0f;
        O2[i][0] = z2; O2[i][1] = z2;
    }

    const int nkb = 2 * qb + 2;   // causal: kv blocks covering keys <= q max
    for (int kb = 0; kb < nkb; kb++) {
        __syncthreads();   // prior Vs/Kt readers done; Qt stored (first iter)

        // Load K (transposed) and V tiles for this kv block.
        {
            const float* kt = kbase + (size_t)(kb * BKV) * D;
            const float* vt = vbase + (size_t)(kb * BKV) * D;
            const int c4 = tid & 15;
#pragma unroll
            for (int it = 0; it < 4; it++) {
                int row = (tid >> 4) + it * 16;     // kv row 0..63
                float4 kv = *reinterpret_cast<const float4*>(kt + (size_t)row * D + c4 * 4);
                Kt[(c4 * 4 + 0) * KST + row] = kv.x;
                Kt[(c4 * 4 + 1) * KST + row] = kv.y;
                Kt[(c4 * 4 + 2) * KST + row] = kv.z;
                Kt[(c4 * 4 + 3) * KST + row] = kv.w;
                float4 vv = *reinterpret_cast<const float4*>(vt + (size_t)row * D + c4 * 4);
                float* vd = Vs + row * 64 + c4 * 4;
                vd[0] = vv.x; vd[1] = vv.y; vd[2] = vv.z; vd[3] = vv.w;
            }
        }
        __syncthreads();

        // Scores: s2[i][p] = sum_d Q[ty*8+i][d] * K[tx*4 + pair p][d]
        u64 s2[8][2];
#pragma unroll
        for (int i = 0; i < 8; i++) { s2[i][0] = z2; s2[i][1] = z2; }

#pragma unroll 8
        for (int d = 0; d < DK; d++) {
            float4 q0 = *reinterpret_cast<const float4*>(Qt + d * QST + ty * 8);
            float4 q1 = *reinterpret_cast<const float4*>(Qt + d * QST + ty * 8 + 4);
            float4 k4 = *reinterpret_cast<const float4*>(Kt + d * KST + tx * 4);
            u64 k01 = pk2(k4.x, k4.y);
            u64 k23 = pk2(k4.z, k4.w);
            float qv[8] = {q0.x, q0.y, q0.z, q0.w, q1.x, q1.y, q1.z, q1.w};
#pragma unroll
            for (int i = 0; i < 8; i++) {
                u64 qd = dup2(qv[i]);
                s2[i][0] = ffma2(qd, k01, s2[i][0]);
                s2[i][1] = ffma2(qd, k23, s2[i][1]);
            }
        }

        // Unpack, scale, mask.
        float s[8][4];
#pragma unroll
        for (int i = 0; i < 8; i++) {
            upk2(s2[i][0], s[i][0], s[i][1]);
            upk2(s2[i][1], s[i][2], s[i][3]);
        }
        const float scale = 0.125f;  // 1/sqrt(64)
#pragma unroll
        for (int i = 0; i < 8; i++)
#pragma unroll
            for (int j = 0; j < 4; j++) s[i][j] *= scale;

        if (kb >= 2 * qb) {   // only the last two blocks touch the diagonal
            const int krow0 = kb * BKV + tx * 4;
            const int qrow0 = 2 * qb * BKV + ty * 8;   // qb*128
#pragma unroll
            for (int i = 0; i < 8; i++)
#pragma unroll
                for (int j = 0; j < 4; j++)
                    if (krow0 + j > qrow0 + i) s[i][j] = -1e30f;
        }

        // Online softmax (row state duplicated across 16 tx lanes).
#pragma unroll
        for (int i = 0; i < 8; i++) {
            float rm = fmaxf(fmaxf(s[i][0], s[i][1]), fmaxf(s[i][2], s[i][3]));
#pragma unroll
            for (int off = 8; off >= 1; off >>= 1)
                rm = fmaxf(rm, __shfl_xor_sync(0xffffffffu, rm, off));
            float mn   = fmaxf(m[i], rm);
            float corr = __expf(m[i] - mn);
            float rs = 0.0f;
#pragma unroll
            for (int j = 0; j < 4; j++) {
                float p = __expf(s[i][j] - mn);
                Pt[(tx * 4 + j) * QST + ty * 8 + i] = p;   // transposed store
                rs += p;
            }
#pragma unroll
            for (int off = 8; off >= 1; off >>= 1)
                rs += __shfl_xor_sync(0xffffffffu, rs, off);
            l[i] = l[i] * corr + rs;
            m[i] = mn;
            u64 cd = dup2(corr);
            O2[i][0] = fmul2(cd, O2[i][0]);
            O2[i][1] = fmul2(cd, O2[i][1]);
        }
        __syncthreads();

        // O2[i][p] += P[row_i][c] * V[c][dim pair p]
#pragma unroll 8
        for (int c = 0; c < BKV; c++) {
            float4 p0 = *reinterpret_cast<const float4*>(Pt + c * QST + ty * 8);
            float4 p1 = *reinterpret_cast<const float4*>(Pt + c * QST + ty * 8 + 4);
            float4 v4 = *reinterpret_cast<const float4*>(Vs + c * 64 + tx * 4);
            u64 v01 = pk2(v4.x, v4.y);
            u64 v23 = pk2(v4.z, v4.w);
            float pr[8] = {p0.x, p0.y, p0.z, p0.w, p1.x, p1.y, p1.z, p1.w};
#pragma unroll
            for (int i = 0; i < 8; i++) {
                u64 pd = dup2(pr[i]);
                O2[i][0] = ffma2(pd, v01, O2[i][0]);
                O2[i][1] = ffma2(pd, v23, O2[i][1]);
            }
        }
    }

    // Normalize, write merged-head output g_x[b, q, h*DK + d] (float4).
#pragma unroll
    for (int i = 0; i < 8; i++) {
        float inv = 1.0f / l[i];
        float o0, o1, o2, o3;
        upk2(O2[i][0], o0, o1);
        upk2(O2[i][1], o2, o3);
        float4 o = {o0 * inv, o1 * inv, o2 * inv, o3 * inv};
        *reinterpret_cast<float4*>(
            g_x + ((size_t)b * S + qb * BQ + ty * 8 + i) * D + h * DK + tx * 4) = o;
    }
}

// ---------------------------------------------------------------------------
// inputs: 0=query 1=key 2=value 3=mask(causal tril, implemented inline)
//         4=Wq 5=bq 6=Wk 7=bk 8=Wv 9=bv 10=Wo 11=bo ; output float [B,S,D]
// ---------------------------------------------------------------------------
extern "C" void kernel_launch(void* const* d_in, const int* in_sizes, int n_in,
                              void* d_out, int out_size)
{
    const float* query = (const float*)d_in[0];
    const float* key   = (const float*)d_in[1];
    const float* value = (const float*)d_in[2];
    const float* Wq = (const float*)d_in[4];
    const float* bq = (const float*)d_in[5];
    const float* Wk = (const float*)d_in[6];
    const float* bk = (const float*)d_in[7];
    const float* Wv = (const float*)d_in[8];
    const float* bv = (const float*)d_in[9];
    const float* Wo = (const float*)d_in[10];
    const float* bo = (const float*)d_in[11];
    float* out = (float*)d_out;

    cudaFuncSetAttribute(attn_kernel,
                         cudaFuncAttributeMaxDynamicSharedMemorySize, 101376);

    dim3 qkv_grid(D / 128, M_TOT / 128, 3);   // (4, 32, 3) = 384 CTAs
    qkv_gemm_kernel<<<qkv_grid, 256>>>(query, key, value,
                                       Wq, bq, Wk, bk, Wv, bv);

    dim3 agrid(S / 128, H, B);                // (16, 8, 2) = 256 CTAs
    attn_kernel<<<agrid, 256, 101376>>>();

    dim3 ogrid(D / 128, M_TOT / 128);         // (4, 32)
    out_gemm_kernel<<<ogrid, 256>>>(Wo, bo, out);
}